// round 13
// baseline (speedup 1.0000x reference)
#include <cuda_runtime.h>

#define DD 8

typedef unsigned long long u64;

// constant layout: [0..63] w | [64..191] ks (per j: 8x KMm, 8x -Km) | [192..223] pl (per j: lj2,alpha,beta,gamma) | [224] sig0
#define C_W   0
#define C_KS  64
#define C_PL  192
#define C_S0  224
#define C_TOT 232

__constant__ __align__(16) u64 cC[C_TOT];

// packed f32x2 ops (Blackwell sm_103a)
#define FMA2(d,a,b,c) asm("fma.rn.f32x2 %0, %1, %2, %3;" : "=l"(d) : "l"(a), "l"(b), "l"(c))
#define MUL2(d,a,b)   asm("mul.rn.f32x2 %0, %1, %2;"     : "=l"(d) : "l"(a), "l"(b))
#define ADD2(d,a,b)   asm("add.rn.f32x2 %0, %1, %2;"     : "=l"(d) : "l"(a), "l"(b))

__device__ __forceinline__ u64 pack2(float lo, float hi) {
    u64 r; asm("mov.b64 %0, {%1, %2};" : "=l"(r) : "f"(lo), "f"(hi)); return r;
}
__device__ __forceinline__ void unpack2(u64 v, float& lo, float& hi) {
    asm("mov.b64 {%0, %1}, %2;" : "=f"(lo), "=f"(hi) : "l"(v));
}
__device__ __forceinline__ float ex2a(float x) {
    float r; asm("ex2.approx.f32 %0, %1;" : "=f"(r) : "f"(x)); return r;
}
__device__ __forceinline__ u64 dup(float v) {
    unsigned u = __float_as_uint(v);
    return ((u64)u << 32) | (u64)u;
}

// ---------- setup kernel: derive constants, write DIRECTLY into cC's backing store ----------
__global__ void setup_kernel(const float* __restrict__ L, const float* __restrict__ sig,
                             u64* __restrict__ cc)
{
    // Let the dependent (main) kernel start launching immediately; its
    // griddepcontrol.wait still blocks until this kernel fully completes.
    asm volatile("griddepcontrol.launch_dependents;");

    int tid = threadIdx.x;            // 0..63
    int c = tid >> 3, j = tid & 7;
    float Ljc = L[j * DD + c];
    float inv2_jc = 1.0f / (Ljc * Ljc);
    float L0c = L[c];
    float inv2_0c = 1.0f / (L0c * L0c);
    float Mcj = inv2_0c + inv2_jc;
    float L0j = L[j];
    float lj2 = L0j * L0j;
    float Kcj = sig[j] / (lj2 * lj2) * Mcj * Mcj;
    cc[C_KS + j * 16 + c]     = dup(Kcj / Mcj);
    cc[C_KS + j * 16 + 8 + c] = dup(-Kcj);
    float Lak = L[c * DD + j];
    cc[C_W + c * DD + j] = dup(-0.5f * 1.44269504088896340736f / (Lak * Lak));
    if (c == j) {
        int l = c;
        float tl = Mcj;                       // M[l][l]
        float c1 = 5.0f * tl + lj2 * tl * tl;
        float c2 = tl * tl;
        float c3 = 2.0f + lj2 * tl;
        float F  = sig[l] / (lj2 * lj2);
        float Kd = Kcj;
        float Md = 1.0f / tl;
        cc[C_PL + l * 4 + 0] = dup(lj2);
        cc[C_PL + l * 4 + 1] = dup(F * c3 - Kd * Md * lj2);    // alpha
        cc[C_PL + l * 4 + 2] = dup(-F * c1 + Kd * (Md + lj2)); // beta
        cc[C_PL + l * 4 + 3] = dup(F * c2 - Kd);               // gamma
    }
    if (tid == 0) cc[C_S0] = dup(sig[0]);
}

// ---------- main kernel ----------
// out[n,m] = sigma0 * E0 * S_total
//   d_k = (x1[n,k]-x2[m,k])^2 ; E_a = exp2( sum_k d_k * w[a,k] )
//   S_total = sum_j E_j * [ acc_j*(lj2_j - d_j) + (alpha + beta d + gamma d^2)_j * E_j ]
//   acc_j = sum_c (KMm[c,j] - Km[c,j] d_c) E_c
//
// Block tile: 8 n-rows x 128 m-cols. 128 threads (32x4).
// Each thread: 2 rows (ty, ty+4) x 2 m-pairs (tx, tx+32) = 4 packed pairs = 8 outputs.
// Constants from the constant bank, loaded as ulonglong2 -> LDC.128 (half the
// LDC count vs u64 loads; const port floor is per-instruction).

__global__ __launch_bounds__(128, 3) void taylor_rbf_kernel(
    const float* __restrict__ x1, const float* __restrict__ x2,
    float* __restrict__ out, int N, int M)
{
    __shared__ __align__(16) u64 x1d[8 * DD];    // dup(x1[n0+r][k]), r=0..7
    __shared__ __align__(16) u64 nx2[DD * 64];   // (-x2[m0+2p][k], -x2[m0+2p+1][k]), p=0..63

    const int tx = threadIdx.x;          // 0..31
    const int ty = threadIdx.y;          // 0..3
    const int tid = ty * 32 + tx;        // 0..127

    // ---- stage x tiles (no cC access here) ----
    const int n0 = blockIdx.y * 8, m0 = blockIdx.x * 128;
#pragma unroll
    for (int i = 0; i < 4; i++) {        // nx2: 512 entries, 4 per thread
        int idx = tid + 128 * i;
        int k = idx >> 6, p = idx & 63;
        int mm = m0 + 2 * p;
        float a = (mm     < M) ? x2[mm * DD + k]       : 0.0f;
        float b = (mm + 1 < M) ? x2[(mm + 1) * DD + k] : 0.0f;
        nx2[k * 64 + p] = pack2(-a, -b);
    }
    if (tid < 64) {                      // x1d: 64 entries
        int r = tid >> 3, k = tid & 7;
        int nn = n0 + r;
        x1d[r * DD + k] = dup((nn < N) ? x1[nn * DD + k] : 0.0f);
    }
    __syncthreads();

    const u64 negone = dup(-1.0f);

    // ---- d for 4 pairs: rows {ty, ty+4}, pair-cols {tx, tx+32} (no cC access) ----
    u64 d[2][2][DD], E[2][2][DD];
#pragma unroll
    for (int k = 0; k < DD; k++) {
        u64 xv0 = nx2[k * 64 + tx];
        u64 xv1 = nx2[k * 64 + tx + 32];
#pragma unroll
        for (int r = 0; r < 2; r++) {
            u64 xr = x1d[(ty + 4 * r) * DD + k];
            u64 f0; ADD2(f0, xr, xv0);  MUL2(d[r][0][k], f0, f0);
            u64 f1; ADD2(f1, xr, xv1);  MUL2(d[r][1][k], f1, f1);
        }
    }

    // ---- PDL sync: setup kernel's constant writes must be visible below ----
    asm volatile("griddepcontrol.wait;" ::: "memory");

    // ---- E_a = exp2( d . w_a ) for 4 pairs (weights via LDC.128) ----
#pragma unroll
    for (int a = 0; a < DD; a++) {
        const ulonglong2* wr = reinterpret_cast<const ulonglong2*>(&cC[C_W + a * DD]);
        ulonglong2 w01 = wr[0], w23 = wr[1], w45 = wr[2], w67 = wr[3];
#pragma unroll
        for (int r = 0; r < 2; r++)
#pragma unroll
        for (int q = 0; q < 2; q++) {
            u64 s;
            MUL2(s, d[r][q][0], w01.x);
            FMA2(s, d[r][q][1], w01.y, s);
            FMA2(s, d[r][q][2], w23.x, s);
            FMA2(s, d[r][q][3], w23.y, s);
            FMA2(s, d[r][q][4], w45.x, s);
            FMA2(s, d[r][q][5], w45.y, s);
            FMA2(s, d[r][q][6], w67.x, s);
            FMA2(s, d[r][q][7], w67.y, s);
            float lo, hi;
            unpack2(s, lo, hi);
            E[r][q][a] = pack2(ex2a(lo), ex2a(hi));
        }
    }

    // ---- merged S + corr loop over j; consts via LDC.128, shared by 4 pairs ----
    u64 S[2][2];
    S[0][0] = S[0][1] = S[1][0] = S[1][1] = dup(0.0f);
#pragma unroll
    for (int j = 0; j < DD; j++) {
        const ulonglong2* kr = reinterpret_cast<const ulonglong2*>(&cC[C_KS + j * 16]);
        ulonglong2 a0 = kr[0], a1 = kr[1], a2 = kr[2], a3 = kr[3]; // KMm
        ulonglong2 b0 = kr[4], b1 = kr[5], b2 = kr[6], b3 = kr[7]; // -Km
        const ulonglong2* pr = reinterpret_cast<const ulonglong2*>(&cC[C_PL + j * 4]);
        ulonglong2 q0 = pr[0];   // (lj2, alpha)
        ulonglong2 q1 = pr[1];   // (beta, gamma)
#pragma unroll
        for (int r = 0; r < 2; r++)
#pragma unroll
        for (int q = 0; q < 2; q++) {
            u64 acc, acc2, wp;
            FMA2(wp, b0.x, d[r][q][0], a0.x);  MUL2(acc,  wp, E[r][q][0]);
            FMA2(wp, b0.y, d[r][q][1], a0.y);  MUL2(acc2, wp, E[r][q][1]);
            FMA2(wp, b1.x, d[r][q][2], a1.x);  FMA2(acc,  wp, E[r][q][2], acc);
            FMA2(wp, b1.y, d[r][q][3], a1.y);  FMA2(acc2, wp, E[r][q][3], acc2);
            FMA2(wp, b2.x, d[r][q][4], a2.x);  FMA2(acc,  wp, E[r][q][4], acc);
            FMA2(wp, b2.y, d[r][q][5], a2.y);  FMA2(acc2, wp, E[r][q][5], acc2);
            FMA2(wp, b3.x, d[r][q][6], a3.x);  FMA2(acc,  wp, E[r][q][6], acc);
            FMA2(wp, b3.y, d[r][q][7], a3.y);  FMA2(acc2, wp, E[r][q][7], acc2);
            ADD2(acc, acc, acc2);

            // S += E_j * ( acc*(lj2-d_j) + (alpha + beta d + gamma d^2) * E_j )
            u64 t;  FMA2(t, d[r][q][j], negone, q0.x);
            u64 u_; FMA2(u_, q1.y, d[r][q][j], q1.x);
            u64 py; FMA2(py, d[r][q][j], u_, q0.y);
            u64 v;  MUL2(v, acc, t);
            FMA2(v, py, E[r][q][j], v);
            FMA2(S[r][q], E[r][q][j], v, S[r][q]);
        }
    }

    // ---- outputs: res = sig0 * E0 * S ----
#pragma unroll
    for (int r = 0; r < 2; r++) {
        int n = n0 + ty + 4 * r;
        if (n >= N) continue;
#pragma unroll
        for (int q = 0; q < 2; q++) {
            int m = m0 + 2 * (tx + 32 * q);
            if (m >= M) continue;
            u64 e0; MUL2(e0, E[r][q][0], cC[C_S0]);
            u64 res; MUL2(res, S[r][q], e0);
            long idx = (long)n * M + m;
            if (m + 1 < M) {
                *reinterpret_cast<u64*>(&out[idx]) = res;
            } else {
                float lo, hi; unpack2(res, lo, hi);
                out[idx] = lo;
            }
        }
    }
}

extern "C" void kernel_launch(void* const* d_in, const int* in_sizes, int n_in,
                              void* d_out, int out_size)
{
    const float* x1  = (const float*)d_in[0];
    const float* x2  = (const float*)d_in[1];
    const float* L   = (const float*)d_in[2];
    const float* sig = (const float*)d_in[3];
    float* out = (float*)d_out;

    int N = in_sizes[0] / DD;
    int M = in_sizes[1] / DD;

    void* cc_addr = nullptr;
    cudaGetSymbolAddress(&cc_addr, cC);
    setup_kernel<<<1, 64>>>(L, sig, (u64*)cc_addr);

    // Main kernel with Programmatic Dependent Launch: overlaps its launch +
    // constant-free preamble with the setup kernel.
    dim3 block(32, 4);                                     // 128 threads
    dim3 grid((M + 127) / 128, (N + 7) / 8);

    cudaLaunchConfig_t cfg = {};
    cfg.gridDim = grid;
    cfg.blockDim = block;
    cfg.dynamicSmemBytes = 0;
    cfg.stream = 0;
    cudaLaunchAttribute attrs[1];
    attrs[0].id = cudaLaunchAttributeProgrammaticStreamSerialization;
    attrs[0].val.programmaticStreamSerializationAllowed = 1;
    cfg.attrs = attrs;
    cfg.numAttrs = 1;

    cudaLaunchKernelEx(&cfg, taylor_rbf_kernel, x1, x2, out, N, M);
}

// round 14
// speedup vs baseline: 1.0266x; 1.0266x over previous
#include <cuda_runtime.h>

#define DD 8

typedef unsigned long long u64;

// constant layout: [0..63] w | [64..191] ks (per j: 8x KMm, 8x -Km) | [192..223] pl (per j: lj2,alpha,beta,gamma) | [224] sig0
#define C_W   0
#define C_KS  64
#define C_PL  192
#define C_S0  224
#define C_TOT 232

__constant__ __align__(16) u64 cC[C_TOT];

// packed f32x2 ops (Blackwell sm_103a)
#define FMA2(d,a,b,c) asm("fma.rn.f32x2 %0, %1, %2, %3;" : "=l"(d) : "l"(a), "l"(b), "l"(c))
#define MUL2(d,a,b)   asm("mul.rn.f32x2 %0, %1, %2;"     : "=l"(d) : "l"(a), "l"(b))
#define ADD2(d,a,b)   asm("add.rn.f32x2 %0, %1, %2;"     : "=l"(d) : "l"(a), "l"(b))

__device__ __forceinline__ u64 pack2(float lo, float hi) {
    u64 r; asm("mov.b64 %0, {%1, %2};" : "=l"(r) : "f"(lo), "f"(hi)); return r;
}
__device__ __forceinline__ void unpack2(u64 v, float& lo, float& hi) {
    asm("mov.b64 {%0, %1}, %2;" : "=f"(lo), "=f"(hi) : "l"(v));
}
__device__ __forceinline__ float ex2a(float x) {
    float r; asm("ex2.approx.f32 %0, %1;" : "=f"(r) : "f"(x)); return r;
}
__device__ __forceinline__ u64 dup(float v) {
    unsigned u = __float_as_uint(v);
    return ((u64)u << 32) | (u64)u;
}

// ---------- setup kernel: derive constants, write DIRECTLY into cC's backing store ----------
__global__ void setup_kernel(const float* __restrict__ L, const float* __restrict__ sig,
                             u64* __restrict__ cc)
{
    // Let the dependent (main) kernel start launching immediately; its
    // griddepcontrol.wait still blocks until this kernel fully completes.
    asm volatile("griddepcontrol.launch_dependents;");

    int tid = threadIdx.x;            // 0..63
    int c = tid >> 3, j = tid & 7;
    float Ljc = L[j * DD + c];
    float inv2_jc = 1.0f / (Ljc * Ljc);
    float L0c = L[c];
    float inv2_0c = 1.0f / (L0c * L0c);
    float Mcj = inv2_0c + inv2_jc;
    float L0j = L[j];
    float lj2 = L0j * L0j;
    float Kcj = sig[j] / (lj2 * lj2) * Mcj * Mcj;
    cc[C_KS + j * 16 + c]     = dup(Kcj / Mcj);
    cc[C_KS + j * 16 + 8 + c] = dup(-Kcj);
    float Lak = L[c * DD + j];
    cc[C_W + c * DD + j] = dup(-0.5f * 1.44269504088896340736f / (Lak * Lak));
    if (c == j) {
        int l = c;
        float tl = Mcj;                       // M[l][l]
        float c1 = 5.0f * tl + lj2 * tl * tl;
        float c2 = tl * tl;
        float c3 = 2.0f + lj2 * tl;
        float F  = sig[l] / (lj2 * lj2);
        float Kd = Kcj;
        float Md = 1.0f / tl;
        cc[C_PL + l * 4 + 0] = dup(lj2);
        cc[C_PL + l * 4 + 1] = dup(F * c3 - Kd * Md * lj2);    // alpha
        cc[C_PL + l * 4 + 2] = dup(-F * c1 + Kd * (Md + lj2)); // beta
        cc[C_PL + l * 4 + 3] = dup(F * c2 - Kd);               // gamma
    }
    if (tid == 0) cc[C_S0] = dup(sig[0]);
}

// ---------- main kernel ----------
// out[n,m] = sigma0 * E0 * S_total
//   d_k = (x1[n,k]-x2[m,k])^2 ; E_a = exp2( sum_k d_k * w[a,k] )
//   S_total = sum_j E_j * [ acc_j*(lj2_j - d_j) + (alpha + beta d + gamma d^2)_j * E_j ]
//   acc_j = sum_c (KMm[c,j] - Km[c,j] d_c) E_c
//
// Block tile: 8 n-rows x 128 m-cols. 128 threads (32x4).
// Each thread: 4 packed pairs p=0..3: row = ty + 4*(p>>1), m-pair col = tx + 32*(p&1).
// All four pairs are EXPLICITLY interleaved at each dependency step so every
// lat-4 FMA2 chain has 3 independent instructions between producer and consumer.

__global__ __launch_bounds__(128, 3) void taylor_rbf_kernel(
    const float* __restrict__ x1, const float* __restrict__ x2,
    float* __restrict__ out, int N, int M)
{
    __shared__ __align__(16) u64 x1d[8 * DD];    // dup(x1[n0+r][k]), r=0..7
    __shared__ __align__(16) u64 nx2[DD * 64];   // (-x2[m0+2p][k], -x2[m0+2p+1][k]), p=0..63

    const int tx = threadIdx.x;          // 0..31
    const int ty = threadIdx.y;          // 0..3
    const int tid = ty * 32 + tx;        // 0..127

    // ---- stage x tiles (no cC access here) ----
    const int n0 = blockIdx.y * 8, m0 = blockIdx.x * 128;
#pragma unroll
    for (int i = 0; i < 4; i++) {        // nx2: 512 entries, 4 per thread
        int idx = tid + 128 * i;
        int k = idx >> 6, p = idx & 63;
        int mm = m0 + 2 * p;
        float a = (mm     < M) ? x2[mm * DD + k]       : 0.0f;
        float b = (mm + 1 < M) ? x2[(mm + 1) * DD + k] : 0.0f;
        nx2[k * 64 + p] = pack2(-a, -b);
    }
    if (tid < 64) {                      // x1d: 64 entries
        int r = tid >> 3, k = tid & 7;
        int nn = n0 + r;
        x1d[r * DD + k] = dup((nn < N) ? x1[nn * DD + k] : 0.0f);
    }
    __syncthreads();

    const u64 negone = dup(-1.0f);

    // ---- d for 4 pairs (p>>1 selects row, p&1 selects m-pair col) ----
    u64 d[4][DD], E[4][DD];
#pragma unroll
    for (int k = 0; k < DD; k++) {
        u64 xv0 = nx2[k * 64 + tx];
        u64 xv1 = nx2[k * 64 + tx + 32];
        u64 xr0 = x1d[ty * DD + k];
        u64 xr1 = x1d[(ty + 4) * DD + k];
        u64 f0, f1, f2, f3;
        ADD2(f0, xr0, xv0);
        ADD2(f1, xr0, xv1);
        ADD2(f2, xr1, xv0);
        ADD2(f3, xr1, xv1);
        MUL2(d[0][k], f0, f0);
        MUL2(d[1][k], f1, f1);
        MUL2(d[2][k], f2, f2);
        MUL2(d[3][k], f3, f3);
    }

    // ---- PDL sync: setup kernel's constant writes must be visible below ----
    asm volatile("griddepcontrol.wait;" ::: "memory");

    // ---- E_a = exp2( d . w_a ): 4 pair-chains interleaved per k-step ----
#pragma unroll
    for (int a = 0; a < DD; a++) {
        const u64* wr = &cC[C_W + a * DD];
        u64 s[4];
#pragma unroll
        for (int p = 0; p < 4; p++) MUL2(s[p], d[p][0], wr[0]);
#pragma unroll
        for (int k = 1; k < DD; k++) {
#pragma unroll
            for (int p = 0; p < 4; p++) FMA2(s[p], d[p][k], wr[k], s[p]);
        }
#pragma unroll
        for (int p = 0; p < 4; p++) {
            float lo, hi;
            unpack2(s[p], lo, hi);
            E[p][a] = pack2(ex2a(lo), ex2a(hi));
        }
    }

    // ---- merged S + corr loop over j; 4 pairs interleaved per c-step ----
    u64 S[4];
    S[0] = S[1] = S[2] = S[3] = dup(0.0f);
#pragma unroll
    for (int j = 0; j < DD; j++) {
        const u64* kmm = &cC[C_KS + j * 16];       // 8x KMm
        const u64* nkm = &cC[C_KS + j * 16 + 8];   // 8x -Km
        const u64* pl  = &cC[C_PL + j * 4];        // lj2, alpha, beta, gamma

        u64 acc[4], acc2[4], wp[4];
        // c = 0 -> acc, c = 1 -> acc2
#pragma unroll
        for (int p = 0; p < 4; p++) FMA2(wp[p], nkm[0], d[p][0], kmm[0]);
#pragma unroll
        for (int p = 0; p < 4; p++) MUL2(acc[p], wp[p], E[p][0]);
#pragma unroll
        for (int p = 0; p < 4; p++) FMA2(wp[p], nkm[1], d[p][1], kmm[1]);
#pragma unroll
        for (int p = 0; p < 4; p++) MUL2(acc2[p], wp[p], E[p][1]);
        // c = 2..7 alternate acc/acc2
#pragma unroll
        for (int c = 2; c < DD; c += 2) {
#pragma unroll
            for (int p = 0; p < 4; p++) FMA2(wp[p], nkm[c], d[p][c], kmm[c]);
#pragma unroll
            for (int p = 0; p < 4; p++) FMA2(acc[p], wp[p], E[p][c], acc[p]);
#pragma unroll
            for (int p = 0; p < 4; p++) FMA2(wp[p], nkm[c + 1], d[p][c + 1], kmm[c + 1]);
#pragma unroll
            for (int p = 0; p < 4; p++) FMA2(acc2[p], wp[p], E[p][c + 1], acc2[p]);
        }
#pragma unroll
        for (int p = 0; p < 4; p++) ADD2(acc[p], acc[p], acc2[p]);

        // tail, interleaved: S += E_j * ( acc*(lj2-d_j) + (alpha + beta d + gamma d^2) * E_j )
        u64 t[4], g[4], py[4], v[4];
#pragma unroll
        for (int p = 0; p < 4; p++) FMA2(t[p], d[p][j], negone, pl[0]);
#pragma unroll
        for (int p = 0; p < 4; p++) FMA2(g[p], pl[3], d[p][j], pl[2]);
#pragma unroll
        for (int p = 0; p < 4; p++) FMA2(py[p], d[p][j], g[p], pl[1]);
#pragma unroll
        for (int p = 0; p < 4; p++) MUL2(v[p], acc[p], t[p]);
#pragma unroll
        for (int p = 0; p < 4; p++) FMA2(v[p], py[p], E[p][j], v[p]);
#pragma unroll
        for (int p = 0; p < 4; p++) FMA2(S[p], E[p][j], v[p], S[p]);
    }

    // ---- outputs: res = sig0 * E0 * S ----
#pragma unroll
    for (int p = 0; p < 4; p++) {
        int n = n0 + ty + 4 * (p >> 1);
        int m = m0 + 2 * (tx + 32 * (p & 1));
        if (n >= N || m >= M) continue;
        u64 e0; MUL2(e0, E[p][0], cC[C_S0]);
        u64 res; MUL2(res, S[p], e0);
        long idx = (long)n * M + m;
        if (m + 1 < M) {
            *reinterpret_cast<u64*>(&out[idx]) = res;
        } else {
            float lo, hi; unpack2(res, lo, hi);
            out[idx] = lo;
        }
    }
}

extern "C" void kernel_launch(void* const* d_in, const int* in_sizes, int n_in,
                              void* d_out, int out_size)
{
    const float* x1  = (const float*)d_in[0];
    const float* x2  = (const float*)d_in[1];
    const float* L   = (const float*)d_in[2];
    const float* sig = (const float*)d_in[3];
    float* out = (float*)d_out;

    int N = in_sizes[0] / DD;
    int M = in_sizes[1] / DD;

    void* cc_addr = nullptr;
    cudaGetSymbolAddress(&cc_addr, cC);
    setup_kernel<<<1, 64>>>(L, sig, (u64*)cc_addr);

    // Main kernel with Programmatic Dependent Launch: overlaps its launch +
    // constant-free preamble with the setup kernel.
    dim3 block(32, 4);                                     // 128 threads
    dim3 grid((M + 127) / 128, (N + 7) / 8);

    cudaLaunchConfig_t cfg = {};
    cfg.gridDim = grid;
    cfg.blockDim = block;
    cfg.dynamicSmemBytes = 0;
    cfg.stream = 0;
    cudaLaunchAttribute attrs[1];
    attrs[0].id = cudaLaunchAttributeProgrammaticStreamSerialization;
    attrs[0].val.programmaticStreamSerializationAllowed = 1;
    cfg.attrs = attrs;
    cfg.numAttrs = 1;

    cudaLaunchKernelEx(&cfg, taylor_rbf_kernel, x1, x2, out, N, M);
}